// round 1
// baseline (speedup 1.0000x reference)
#include <cuda_runtime.h>
#include <math.h>

#define D   1024
#define H   16
#define HD  64
#define B   2
#define SQ  2048
#define M   (B * SQ)      // 4096 rows

// ---------------- scratch (allocation-free rule: __device__ globals) --------
__device__ float g_Q[B * H * SQ * HD];   // [B,H,S,HD], pre-scaled by 1/sqrt(HD)
__device__ float g_K[B * H * SQ * HD];
__device__ float g_V[B * H * SQ * HD];
__device__ float g_O[B * H * SQ * HD];   // attention output, head layout

// ---------------- GEMM tiling ------------------------------------------------
#define BM 64
#define BN 64
#define BK 16
// 256 threads = 16x16, each computes 4x4

// ========== Kernel 1: fused QKV projection, epilogue -> head layout ==========
__global__ __launch_bounds__(256)
void qkv_kernel(const float* __restrict__ X,
                const float* __restrict__ Wq, const float* __restrict__ bq,
                const float* __restrict__ Wk, const float* __restrict__ bk,
                const float* __restrict__ Wv, const float* __restrict__ bv)
{
    const float* W; const float* bias; float* out; float scale;
    if (blockIdx.z == 0)      { W = Wq; bias = bq; out = g_Q; scale = 0.125f; } // 1/sqrt(64)
    else if (blockIdx.z == 1) { W = Wk; bias = bk; out = g_K; scale = 1.0f; }
    else                      { W = Wv; bias = bv; out = g_V; scale = 1.0f; }

    __shared__ float As[BK][BM + 1];
    __shared__ float Bs[BK][BN + 1];

    const int block_m = blockIdx.y * BM;
    const int block_n = blockIdx.x * BN;
    const int tid = threadIdx.x;
    const int tx = tid & 15, ty = tid >> 4;

    float acc[4][4] = {};

    for (int k0 = 0; k0 < D; k0 += BK) {
        #pragma unroll
        for (int i = tid; i < BM * BK; i += 256) {
            int m = i / BK, k = i % BK;
            As[k][m] = X[(block_m + m) * D + k0 + k];
        }
        #pragma unroll
        for (int i = tid; i < BK * BN; i += 256) {
            int k = i / BN, n = i % BN;
            Bs[k][n] = W[(k0 + k) * D + block_n + n];
        }
        __syncthreads();
        #pragma unroll
        for (int k = 0; k < BK; k++) {
            float a[4], b[4];
            #pragma unroll
            for (int i = 0; i < 4; i++) a[i] = As[k][ty * 4 + i];
            #pragma unroll
            for (int j = 0; j < 4; j++) b[j] = Bs[k][tx * 4 + j];
            #pragma unroll
            for (int i = 0; i < 4; i++)
                #pragma unroll
                for (int j = 0; j < 4; j++)
                    acc[i][j] += a[i] * b[j];
        }
        __syncthreads();
    }

    #pragma unroll
    for (int i = 0; i < 4; i++) {
        int m = block_m + ty * 4 + i;
        int bb = m >> 11, s = m & (SQ - 1);
        #pragma unroll
        for (int j = 0; j < 4; j++) {
            int n = block_n + tx * 4 + j;
            int h = n >> 6, d = n & (HD - 1);
            out[(((bb * H + h) * SQ) + s) * HD + d] = (acc[i][j] + bias[n]) * scale;
        }
    }
}

// ========== Kernel 2: flash attention, 1 block per (bh, 64-query tile) ======
#define BQ  64
#define BKV 32

__global__ __launch_bounds__(256)
void attn_kernel()
{
    __shared__ float Qs[HD][BQ + 1];    // [d][q]
    __shared__ float Ks[HD][BKV + 1];   // [d][j]
    __shared__ float Vs[BKV][HD + 1];   // [j][d]
    __shared__ float Ss[BQ][BKV + 1];   // [q][j]
    __shared__ float m_s[BQ], l_s[BQ], corr_s[BQ];

    const int bh = blockIdx.y;                 // b*H + h
    const int q0 = blockIdx.x * BQ;
    const float* Qg = g_Q + (bh * SQ + q0) * HD;
    const float* Kg = g_K + bh * SQ * HD;
    const float* Vg = g_V + bh * SQ * HD;

    const int tid = threadIdx.x;
    const int tx = tid & 15, ty = tid >> 4;

    #pragma unroll
    for (int i = tid; i < BQ * HD; i += 256) {
        int q = i >> 6, d = i & (HD - 1);
        Qs[d][q] = Qg[q * HD + d];
    }
    if (tid < BQ) { m_s[tid] = -1e30f; l_s[tid] = 0.0f; }

    float o[4][4] = {};
    __syncthreads();

    for (int kv0 = 0; kv0 < SQ; kv0 += BKV) {
        #pragma unroll
        for (int i = tid; i < BKV * HD; i += 256) {
            int j = i >> 6, d = i & (HD - 1);
            float kv = Kg[(kv0 + j) * HD + d];
            float vv = Vg[(kv0 + j) * HD + d];
            Ks[d][j] = kv;
            Vs[j][d] = vv;
        }
        __syncthreads();

        // scores: rows ty*4+i, cols tx*2+jj   (64x32 tile, Q pre-scaled)
        float acc[4][2] = {};
        #pragma unroll 16
        for (int d = 0; d < HD; d++) {
            float a[4], b[2];
            #pragma unroll
            for (int i = 0; i < 4; i++) a[i] = Qs[d][ty * 4 + i];
            #pragma unroll
            for (int jj = 0; jj < 2; jj++) b[jj] = Ks[d][tx * 2 + jj];
            #pragma unroll
            for (int i = 0; i < 4; i++)
                #pragma unroll
                for (int jj = 0; jj < 2; jj++)
                    acc[i][jj] += a[i] * b[jj];
        }
        #pragma unroll
        for (int i = 0; i < 4; i++)
            #pragma unroll
            for (int jj = 0; jj < 2; jj++)
                Ss[ty * 4 + i][tx * 2 + jj] = acc[i][jj];
        __syncthreads();

        // online softmax per row (64 rows handled by first 2 warps)
        if (tid < BQ) {
            int r = tid;
            float mold = m_s[r];
            float mnew = mold;
            #pragma unroll
            for (int j = 0; j < BKV; j++) mnew = fmaxf(mnew, Ss[r][j]);
            float corr = __expf(mold - mnew);
            float l = l_s[r] * corr;
            #pragma unroll
            for (int j = 0; j < BKV; j++) {
                float p = __expf(Ss[r][j] - mnew);
                Ss[r][j] = p;
                l += p;
            }
            m_s[r] = mnew; l_s[r] = l; corr_s[r] = corr;
        }
        __syncthreads();

        // rescale existing accumulator and add P @ V
        float c[4];
        #pragma unroll
        for (int i = 0; i < 4; i++) c[i] = corr_s[ty * 4 + i];
        #pragma unroll
        for (int i = 0; i < 4; i++)
            #pragma unroll
            for (int j = 0; j < 4; j++)
                o[i][j] *= c[i];

        #pragma unroll 8
        for (int j = 0; j < BKV; j++) {
            float a[4], b[4];
            #pragma unroll
            for (int i = 0; i < 4; i++) a[i] = Ss[ty * 4 + i][j];
            #pragma unroll
            for (int dd = 0; dd < 4; dd++) b[dd] = Vs[j][tx * 4 + dd];
            #pragma unroll
            for (int i = 0; i < 4; i++)
                #pragma unroll
                for (int dd = 0; dd < 4; dd++)
                    o[i][dd] += a[i] * b[dd];
        }
        __syncthreads();
    }

    float* Og = g_O + (bh * SQ + q0) * HD;
    #pragma unroll
    for (int i = 0; i < 4; i++) {
        float inv_l = 1.0f / l_s[ty * 4 + i];
        #pragma unroll
        for (int dd = 0; dd < 4; dd++)
            Og[(ty * 4 + i) * HD + tx * 4 + dd] = o[i][dd] * inv_l;
    }
}

// ========== Kernel 3: output projection (concat-permute folded into A load) ==
__global__ __launch_bounds__(256)
void out_kernel(const float* __restrict__ Wo, const float* __restrict__ bo,
                float* __restrict__ Y)
{
    __shared__ float As[BK][BM + 1];
    __shared__ float Bs[BK][BN + 1];

    const int block_m = blockIdx.y * BM;
    const int block_n = blockIdx.x * BN;
    const int tid = threadIdx.x;
    const int tx = tid & 15, ty = tid >> 4;

    float acc[4][4] = {};

    for (int k0 = 0; k0 < D; k0 += BK) {
        #pragma unroll
        for (int i = tid; i < BM * BK; i += 256) {
            int m = i / BK, k = i % BK;
            int mm = block_m + m;
            int bb = mm >> 11, s = mm & (SQ - 1);
            int kk = k0 + k;
            int h = kk >> 6, dd = kk & (HD - 1);
            As[k][m] = g_O[(((bb * H + h) * SQ) + s) * HD + dd];
        }
        #pragma unroll
        for (int i = tid; i < BK * BN; i += 256) {
            int k = i / BN, n = i % BN;
            Bs[k][n] = Wo[(k0 + k) * D + block_n + n];
        }
        __syncthreads();
        #pragma unroll
        for (int k = 0; k < BK; k++) {
            float a[4], b[4];
            #pragma unroll
            for (int i = 0; i < 4; i++) a[i] = As[k][ty * 4 + i];
            #pragma unroll
            for (int j = 0; j < 4; j++) b[j] = Bs[k][tx * 4 + j];
            #pragma unroll
            for (int i = 0; i < 4; i++)
                #pragma unroll
                for (int j = 0; j < 4; j++)
                    acc[i][j] += a[i] * b[j];
        }
        __syncthreads();
    }

    #pragma unroll
    for (int i = 0; i < 4; i++) {
        int m = block_m + ty * 4 + i;
        #pragma unroll
        for (int j = 0; j < 4; j++) {
            int n = block_n + tx * 4 + j;
            Y[m * D + n] = acc[i][j] + bo[n];
        }
    }
}

// ---------------------------------------------------------------------------
extern "C" void kernel_launch(void* const* d_in, const int* in_sizes, int n_in,
                              void* d_out, int out_size)
{
    const float* X  = (const float*)d_in[0];
    const float* Wq = (const float*)d_in[1];
    const float* bq = (const float*)d_in[2];
    const float* Wk = (const float*)d_in[3];
    const float* bk = (const float*)d_in[4];
    const float* Wv = (const float*)d_in[5];
    const float* bv = (const float*)d_in[6];
    const float* Wo = (const float*)d_in[7];
    const float* bo = (const float*)d_in[8];
    float* Y = (float*)d_out;

    dim3 gProj(D / BN, M / BM, 3);       // 16 x 64 x 3
    qkv_kernel<<<gProj, 256>>>(X, Wq, bq, Wk, bk, Wv, bv);

    dim3 gAttn(SQ / BQ, B * H);          // 32 x 32
    attn_kernel<<<gAttn, 256>>>();

    dim3 gOut(D / BN, M / BM);           // 16 x 64
    out_kernel<<<gOut, 256>>>(Wo, bo, Y);
}

// round 4
// speedup vs baseline: 1.4450x; 1.4450x over previous
#include <cuda_runtime.h>
#include <cuda_bf16.h>
#include <cstdint>
#include <math.h>

#define D   1024
#define H   16
#define HD  64
#define B   2
#define SQ  2048
#define M   (B * SQ)      // 4096 rows

// ---------------- scratch (allocation-free rule: __device__ globals) --------
__device__ float g_Q[B * H * SQ * HD];   // [B,H,S,HD], pre-scaled by 1/sqrt(HD)
__device__ float g_K[B * H * SQ * HD];
__device__ float g_V[B * H * SQ * HD];
__device__ float g_O[B * H * SQ * HD];   // attention output, head layout

// bf16 hi/lo decompositions (packed bf16x2, low 16 bits = even k)
__device__ uint32_t g_Xh[M * D / 2];         // inputs [m][k]
__device__ uint32_t g_Xl[M * D / 2];
__device__ uint32_t g_Wth[4 * D * D / 2];    // weights transposed [n][k], z-major
__device__ uint32_t g_Wtl[4 * D * D / 2];
__device__ uint32_t g_Oh[M * D / 2];         // attention out, permuted to [m][k]
__device__ uint32_t g_Ol[M * D / 2];

// =================== helpers ================================================
__device__ __forceinline__ void split1(float x, __nv_bfloat16& h, __nv_bfloat16& l) {
    h = __float2bfloat16_rn(x);
    l = __float2bfloat16_rn(x - __bfloat162float(h));
}
__device__ __forceinline__ uint32_t pack2(__nv_bfloat16 a, __nv_bfloat16 b) {
    __nv_bfloat162 p = __halves2bfloat162(a, b);   // a -> low 16 bits
    return *(uint32_t*)&p;
}
__device__ __forceinline__ void mma_bf16(float* c, const uint32_t* a, const uint32_t* b) {
    asm volatile(
        "mma.sync.aligned.m16n8k16.row.col.f32.bf16.bf16.f32 "
        "{%0,%1,%2,%3}, {%4,%5,%6,%7}, {%8,%9}, {%0,%1,%2,%3};"
        : "+f"(c[0]), "+f"(c[1]), "+f"(c[2]), "+f"(c[3])
        : "r"(a[0]), "r"(a[1]), "r"(a[2]), "r"(a[3]), "r"(b[0]), "r"(b[1]));
}

// ================ split kernels =============================================
__global__ __launch_bounds__(256)
void split_x_kernel(const float* __restrict__ X)
{
    int i = blockIdx.x * 256 + threadIdx.x;        // pair index over [m][k/2]
    float2 v = *(const float2*)(X + 2 * i);
    __nv_bfloat16 h0, l0, h1, l1;
    split1(v.x, h0, l0); split1(v.y, h1, l1);
    g_Xh[i] = pack2(h0, h1);
    g_Xl[i] = pack2(l0, l1);
}

__global__ __launch_bounds__(256)
void split_w_kernel(const float* __restrict__ W0, const float* __restrict__ W1,
                    const float* __restrict__ W2, const float* __restrict__ W3)
{
    __shared__ float t[32][33];
    const float* src = (blockIdx.z == 0) ? W0 : (blockIdx.z == 1) ? W1
                     : (blockIdx.z == 2) ? W2 : W3;
    const int tx = threadIdx.x & 31, ty = threadIdx.x >> 5;   // 32 x 8
    const int k0 = blockIdx.y * 32, n0 = blockIdx.x * 32;
    #pragma unroll
    for (int i = ty; i < 32; i += 8)
        t[i][tx] = src[(k0 + i) * D + n0 + tx];    // t[k_local][n_local]
    __syncthreads();
    uint32_t* dh = g_Wth + blockIdx.z * (D * D / 2);
    uint32_t* dl = g_Wtl + blockIdx.z * (D * D / 2);
    #pragma unroll
    for (int i2 = 0; i2 < 2; i2++) {
        int oidx = threadIdx.x + i2 * 256;
        int nl = oidx >> 4, kp = oidx & 15;
        __nv_bfloat16 h0, l0, h1, l1;
        split1(t[2 * kp][nl], h0, l0);
        split1(t[2 * kp + 1][nl], h1, l1);
        int o = (n0 + nl) * (D / 2) + (k0 >> 1) + kp;
        dh[o] = pack2(h0, h1);
        dl[o] = pack2(l0, l1);
    }
}

__global__ __launch_bounds__(256)
void split_o_kernel()
{
    int i = blockIdx.x * 256 + threadIdx.x;        // pair index over [m][k/2]
    int m = i >> 9, kp = i & 511;
    int k = kp * 2;
    int bb = m >> 11, s = m & (SQ - 1), h = k >> 6, dd = k & (HD - 1);
    float2 v = *(const float2*)(g_O + (((bb * H + h) * SQ) + s) * HD + dd);
    __nv_bfloat16 h0, l0, h1, l1;
    split1(v.x, h0, l0); split1(v.y, h1, l1);
    g_Oh[i] = pack2(h0, h1);
    g_Ol[i] = pack2(l0, l1);
}

// ================ bf16 3-term GEMM ==========================================
#define GBM 128
#define GBN 128
#define GBK 32            // bf16 elems per k-iter (2 k16 mma steps)
#define KP  (GBK / 2)     // 16 uint32 pairs per row per iter
#define NKB (D / GBK)     // 32
#define TST 20            // smem row stride in uint32 (bank-conflict-free)

// One CTA = 128x128 tile, 8 warps of 64x32, 3-term bf16 mma
// A = [m][k] hi/lo (gAh/gAl), B = [n][k] hi/lo (gBh/gBl)
#define GEMM_BODY(gAh, gAl, gBh, gBl, AROW_EXPR)                                   \
    __shared__ uint32_t Ash[GBM][TST], Asl[GBM][TST];                              \
    __shared__ uint32_t Bsh[GBN][TST], Bsl[GBN][TST];                              \
    const int tid  = threadIdx.x;                                                  \
    const int lane = tid & 31;                                                     \
    const int wid  = tid >> 5;                                                     \
    const int warp_m = (wid >> 2) * 64;                                            \
    const int warp_n = (wid & 3) * 32;                                             \
    const int m0 = blockIdx.y * GBM;                                               \
    const int n0 = blockIdx.x * GBN;                                               \
    float c[4][4][4] = {};                                                         \
    uint32_t pah[8], pal[8], pbh[8], pbl[8];                                       \
    {                                                                              \
        const int kcol = 0;                                                        \
        _Pragma("unroll")                                                          \
        for (int i = 0; i < 8; i++) {                                              \
            int idx = tid + i * 256;                                               \
            int r = idx >> 4, kp = idx & 15;                                       \
            int arow = AROW_EXPR;                                                  \
            pah[i] = gAh[arow * (D / 2) + kcol + kp];                              \
            pal[i] = gAl[arow * (D / 2) + kcol + kp];                              \
            pbh[i] = gBh[(n0 + r) * (D / 2) + kcol + kp];                          \
            pbl[i] = gBl[(n0 + r) * (D / 2) + kcol + kp];                          \
        }                                                                          \
    }                                                                              \
    for (int kb = 0; kb < NKB; kb++) {                                             \
        _Pragma("unroll")                                                          \
        for (int i = 0; i < 8; i++) {                                              \
            int idx = tid + i * 256;                                               \
            int r = idx >> 4, kp = idx & 15;                                       \
            Ash[r][kp] = pah[i]; Asl[r][kp] = pal[i];                              \
            Bsh[r][kp] = pbh[i]; Bsl[r][kp] = pbl[i];                              \
        }                                                                          \
        __syncthreads();                                                           \
        if (kb + 1 < NKB) {                                                        \
            const int kcol = (kb + 1) * KP;                                        \
            _Pragma("unroll")                                                      \
            for (int i = 0; i < 8; i++) {                                          \
                int idx = tid + i * 256;                                           \
                int r = idx >> 4, kp = idx & 15;                                   \
                int arow = AROW_EXPR;                                              \
                pah[i] = gAh[arow * (D / 2) + kcol + kp];                          \
                pal[i] = gAl[arow * (D / 2) + kcol + kp];                          \
                pbh[i] = gBh[(n0 + r) * (D / 2) + kcol + kp];                      \
                pbl[i] = gBl[(n0 + r) * (D / 2) + kcol + kp];                      \
            }                                                                      \
        }                                                                          \
        _Pragma("unroll")                                                          \
        for (int ks = 0; ks < 2; ks++) {                                           \
            const int kp0 = ks * 8;                                                \
            uint32_t ah[4][4], al[4][4], bh[4][2], bl[4][2];                       \
            _Pragma("unroll")                                                      \
            for (int t = 0; t < 4; t++) {                                          \
                int r = warp_m + t * 16 + (lane >> 2);                             \
                int q = kp0 + (lane & 3);                                          \
                ah[t][0] = Ash[r][q];     al[t][0] = Asl[r][q];                    \
                ah[t][1] = Ash[r + 8][q]; al[t][1] = Asl[r + 8][q];                \
                ah[t][2] = Ash[r][q + 4]; al[t][2] = Asl[r][q + 4];                \
                ah[t][3] = Ash[r + 8][q + 4]; al[t][3] = Asl[r + 8][q + 4];        \
            }                                                                      \
            _Pragma("unroll")                                                      \
            for (int u = 0; u < 4; u++) {                                          \
                int n = warp_n + u * 8 + (lane >> 2);                              \
                int q = kp0 + (lane & 3);                                          \
                bh[u][0] = Bsh[n][q];     bh[u][1] = Bsh[n][q + 4];                \
                bl[u][0] = Bsl[n][q];     bl[u][1] = Bsl[n][q + 4];                \
            }                                                                      \
            _Pragma("unroll")                                                      \
            for (int t = 0; t < 4; t++)                                            \
                _Pragma("unroll")                                                  \
                for (int u = 0; u < 4; u++) {                                      \
                    mma_bf16(c[t][u], ah[t], bh[u]);                               \
                    mma_bf16(c[t][u], ah[t], bl[u]);                               \
                    mma_bf16(c[t][u], al[t], bh[u]);                               \
                }                                                                  \
        }                                                                          \
        __syncthreads();                                                           \
    }

// ---- Kernel 1: fused QKV projection --------------------------------------
__global__ __launch_bounds__(256, 1)
void qkv_mma_kernel(const float* __restrict__ bq, const float* __restrict__ bk,
                    const float* __restrict__ bv)
{
    const float* bias; float* out; float scale;
    const uint32_t* wh = g_Wth + blockIdx.z * (D * D / 2);
    const uint32_t* wl = g_Wtl + blockIdx.z * (D * D / 2);
    if (blockIdx.z == 0)      { bias = bq; out = g_Q; scale = 0.125f; }
    else if (blockIdx.z == 1) { bias = bk; out = g_K; scale = 1.0f; }
    else                      { bias = bv; out = g_V; scale = 1.0f; }

    GEMM_BODY(g_Xh, g_Xl, wh, wl, (m0 + r))

    // epilogue: bias + scale + head-layout scatter
    #pragma unroll
    for (int t = 0; t < 4; t++) {
        int r = warp_m + t * 16 + (lane >> 2);
        #pragma unroll
        for (int half = 0; half < 2; half++) {
            int m = m0 + r + half * 8;
            int bb = m >> 11, s = m & (SQ - 1);
            #pragma unroll
            for (int u = 0; u < 4; u++) {
                int n = n0 + warp_n + u * 8 + 2 * (lane & 3);
                int h = n >> 6, dd = n & (HD - 1);
                float* o = out + (((bb * H + h) * SQ) + s) * HD + dd;
                o[0] = (c[t][u][half * 2 + 0] + bias[n])     * scale;
                o[1] = (c[t][u][half * 2 + 1] + bias[n + 1]) * scale;
            }
        }
    }
}

// ---- Kernel 3: output projection ------------------------------------------
__global__ __launch_bounds__(256, 1)
void out_mma_kernel(const float* __restrict__ bo, float* __restrict__ Y)
{
    const uint32_t* wh = g_Wth + 3 * (D * D / 2);
    const uint32_t* wl = g_Wtl + 3 * (D * D / 2);

    GEMM_BODY(g_Oh, g_Ol, wh, wl, (m0 + r))

    #pragma unroll
    for (int t = 0; t < 4; t++) {
        int r = warp_m + t * 16 + (lane >> 2);
        #pragma unroll
        for (int half = 0; half < 2; half++) {
            int m = m0 + r + half * 8;
            #pragma unroll
            for (int u = 0; u < 4; u++) {
                int n = n0 + warp_n + u * 8 + 2 * (lane & 3);
                Y[m * D + n]     = c[t][u][half * 2 + 0] + bo[n];
                Y[m * D + n + 1] = c[t][u][half * 2 + 1] + bo[n + 1];
            }
        }
    }
}

// ========== Kernel 2: flash attention (unchanged, SIMT fp32) ================
#define BQ  64
#define BKV 32

__global__ __launch_bounds__(256)
void attn_kernel()
{
    __shared__ float Qs[HD][BQ + 1];    // [d][q]
    __shared__ float Ks[HD][BKV + 1];   // [d][j]
    __shared__ float Vs[BKV][HD + 1];   // [j][d]
    __shared__ float Ss[BQ][BKV + 1];   // [q][j]
    __shared__ float m_s[BQ], l_s[BQ], corr_s[BQ];

    const int bh = blockIdx.y;                 // b*H + h
    const int q0 = blockIdx.x * BQ;
    const float* Qg = g_Q + (bh * SQ + q0) * HD;
    const float* Kg = g_K + bh * SQ * HD;
    const float* Vg = g_V + bh * SQ * HD;

    const int tid = threadIdx.x;
    const int tx = tid & 15, ty = tid >> 4;

    #pragma unroll
    for (int i = tid; i < BQ * HD; i += 256) {
        int q = i >> 6, d = i & (HD - 1);
        Qs[d][q] = Qg[q * HD + d];
    }
    if (tid < BQ) { m_s[tid] = -1e30f; l_s[tid] = 0.0f; }

    float o[4][4] = {};
    __syncthreads();

    for (int kv0 = 0; kv0 < SQ; kv0 += BKV) {
        #pragma unroll
        for (int i = tid; i < BKV * HD; i += 256) {
            int j = i >> 6, d = i & (HD - 1);
            float kv = Kg[(kv0 + j) * HD + d];
            float vv = Vg[(kv0 + j) * HD + d];
            Ks[d][j] = kv;
            Vs[j][d] = vv;
        }
        __syncthreads();

        float acc[4][2] = {};
        #pragma unroll 16
        for (int d = 0; d < HD; d++) {
            float a[4], b[2];
            #pragma unroll
            for (int i = 0; i < 4; i++) a[i] = Qs[d][ty * 4 + i];
            #pragma unroll
            for (int jj = 0; jj < 2; jj++) b[jj] = Ks[d][tx * 2 + jj];
            #pragma unroll
            for (int i = 0; i < 4; i++)
                #pragma unroll
                for (int jj = 0; jj < 2; jj++)
                    acc[i][jj] += a[i] * b[jj];
        }
        #pragma unroll
        for (int i = 0; i < 4; i++)
            #pragma unroll
            for (int jj = 0; jj < 2; jj++)
                Ss[ty * 4 + i][tx * 2 + jj] = acc[i][jj];
        __syncthreads();

        if (tid < BQ) {
            int r = tid;
            float mold = m_s[r];
            float mnew = mold;
            #pragma unroll
            for (int j = 0; j < BKV; j++) mnew = fmaxf(mnew, Ss[r][j]);
            float corr = __expf(mold - mnew);
            float l = l_s[r] * corr;
            #pragma unroll
            for (int j = 0; j < BKV; j++) {
                float p = __expf(Ss[r][j] - mnew);
                Ss[r][j] = p;
                l += p;
            }
            m_s[r] = mnew; l_s[r] = l; corr_s[r] = corr;
        }
        __syncthreads();

        float cc[4];
        #pragma unroll
        for (int i = 0; i < 4; i++) cc[i] = corr_s[ty * 4 + i];
        #pragma unroll
        for (int i = 0; i < 4; i++)
            #pragma unroll
            for (int j = 0; j < 4; j++)
                o[i][j] *= cc[i];

        #pragma unroll 8
        for (int j = 0; j < BKV; j++) {
            float a[4], b[4];
            #pragma unroll
            for (int i = 0; i < 4; i++) a[i] = Ss[ty * 4 + i][j];
            #pragma unroll
            for (int dd = 0; dd < 4; dd++) b[dd] = Vs[j][tx * 4 + dd];
            #pragma unroll
            for (int i = 0; i < 4; i++)
                #pragma unroll
                for (int dd = 0; dd < 4; dd++)
                    o[i][dd] += a[i] * b[dd];
        }
        __syncthreads();
    }

    float* Og = g_O + (bh * SQ + q0) * HD;
    #pragma unroll
    for (int i = 0; i < 4; i++) {
        float inv_l = 1.0f / l_s[ty * 4 + i];
        #pragma unroll
        for (int dd = 0; dd < 4; dd++)
            Og[(ty * 4 + i) * HD + tx * 4 + dd] = o[i][dd] * inv_l;
    }
}

// ---------------------------------------------------------------------------
extern "C" void kernel_launch(void* const* d_in, const int* in_sizes, int n_in,
                              void* d_out, int out_size)
{
    const float* X  = (const float*)d_in[0];
    const float* Wq = (const float*)d_in[1];
    const float* bq = (const float*)d_in[2];
    const float* Wk = (const float*)d_in[3];
    const float* bk = (const float*)d_in[4];
    const float* Wv = (const float*)d_in[5];
    const float* bv = (const float*)d_in[6];
    const float* Wo = (const float*)d_in[7];
    const float* bo = (const float*)d_in[8];
    float* Y = (float*)d_out;

    split_x_kernel<<<M * D / 2 / 256, 256>>>(X);
    dim3 gW(D / 32, D / 32, 4);
    split_w_kernel<<<gW, 256>>>(Wq, Wk, Wv, Wo);

    dim3 gQKV(D / GBN, M / GBM, 3);                // 8 x 32 x 3
    qkv_mma_kernel<<<gQKV, 256>>>(bq, bk, bv);

    dim3 gAttn(SQ / BQ, B * H);                    // 32 x 32
    attn_kernel<<<gAttn, 256>>>();

    split_o_kernel<<<M * D / 2 / 256, 256>>>();

    dim3 gOut(D / GBN, M / GBM);                   // 8 x 32
    out_mma_kernel<<<gOut, 256>>>(bo, Y);
}

// round 5
// speedup vs baseline: 2.8929x; 2.0020x over previous
#include <cuda_runtime.h>
#include <cuda_bf16.h>
#include <cstdint>
#include <math.h>

#define D   1024
#define H   16
#define HD  64
#define B   2
#define SQ  2048
#define M   (B * SQ)      // 4096 rows

// ---------------- scratch (allocation-free rule: __device__ globals) --------
// bf16 hi/lo decompositions (packed bf16x2, low 16 bits = even index)
__device__ uint32_t g_Xh[M * D / 2];         // inputs [m][k]
__device__ uint32_t g_Xl[M * D / 2];
__device__ uint32_t g_Wth[4 * D * D / 2];    // weights transposed [n][k], z-major
__device__ uint32_t g_Wtl[4 * D * D / 2];
// Q/K/V in head layout [bh][s][d/2], Q pre-scaled by 1/sqrt(HD)
__device__ uint32_t g_Qh[B * H * SQ * 32];
__device__ uint32_t g_Ql[B * H * SQ * 32];
__device__ uint32_t g_Kh[B * H * SQ * 32];
__device__ uint32_t g_Kl[B * H * SQ * 32];
__device__ uint32_t g_Vh[B * H * SQ * 32];
__device__ uint32_t g_Vl[B * H * SQ * 32];
// attention output, permuted to [m][k/2] for out projection
__device__ uint32_t g_Oh[M * D / 2];
__device__ uint32_t g_Ol[M * D / 2];

// =================== helpers ================================================
__device__ __forceinline__ void split1(float x, __nv_bfloat16& h, __nv_bfloat16& l) {
    h = __float2bfloat16_rn(x);
    l = __float2bfloat16_rn(x - __bfloat162float(h));
}
__device__ __forceinline__ uint32_t pack2(__nv_bfloat16 a, __nv_bfloat16 b) {
    __nv_bfloat162 p = __halves2bfloat162(a, b);   // a -> low 16 bits
    return *(uint32_t*)&p;
}
__device__ __forceinline__ void mma_bf16(float* c, const uint32_t* a, const uint32_t* b) {
    asm volatile(
        "mma.sync.aligned.m16n8k16.row.col.f32.bf16.bf16.f32 "
        "{%0,%1,%2,%3}, {%4,%5,%6,%7}, {%8,%9}, {%0,%1,%2,%3};"
        : "+f"(c[0]), "+f"(c[1]), "+f"(c[2]), "+f"(c[3])
        : "r"(a[0]), "r"(a[1]), "r"(a[2]), "r"(a[3]), "r"(b[0]), "r"(b[1]));
}
__device__ __forceinline__ uint32_t smem_u32(const void* p) {
    uint32_t a;
    asm("{ .reg .u64 t; cvta.to.shared.u64 t, %1; cvt.u32.u64 %0, t; }" : "=r"(a) : "l"(p));
    return a;
}
__device__ __forceinline__ void ldmx2t(uint32_t& r0, uint32_t& r1, uint32_t a) {
    asm volatile("ldmatrix.sync.aligned.m8n8.x2.trans.shared.b16 {%0,%1}, [%2];"
                 : "=r"(r0), "=r"(r1) : "r"(a));
}

// ================ split kernels =============================================
__global__ __launch_bounds__(256)
void split_x_kernel(const float* __restrict__ X)
{
    int i = blockIdx.x * 256 + threadIdx.x;        // pair index over [m][k/2]
    float2 v = *(const float2*)(X + 2 * i);
    __nv_bfloat16 h0, l0, h1, l1;
    split1(v.x, h0, l0); split1(v.y, h1, l1);
    g_Xh[i] = pack2(h0, h1);
    g_Xl[i] = pack2(l0, l1);
}

__global__ __launch_bounds__(256)
void split_w_kernel(const float* __restrict__ W0, const float* __restrict__ W1,
                    const float* __restrict__ W2, const float* __restrict__ W3)
{
    __shared__ float t[32][33];
    const float* src = (blockIdx.z == 0) ? W0 : (blockIdx.z == 1) ? W1
                     : (blockIdx.z == 2) ? W2 : W3;
    const int tx = threadIdx.x & 31, ty = threadIdx.x >> 5;   // 32 x 8
    const int k0 = blockIdx.y * 32, n0 = blockIdx.x * 32;
    #pragma unroll
    for (int i = ty; i < 32; i += 8)
        t[i][tx] = src[(k0 + i) * D + n0 + tx];    // t[k_local][n_local]
    __syncthreads();
    uint32_t* dh = g_Wth + blockIdx.z * (D * D / 2);
    uint32_t* dl = g_Wtl + blockIdx.z * (D * D / 2);
    #pragma unroll
    for (int i2 = 0; i2 < 2; i2++) {
        int oidx = threadIdx.x + i2 * 256;
        int nl = oidx >> 4, kp = oidx & 15;
        __nv_bfloat16 h0, l0, h1, l1;
        split1(t[2 * kp][nl], h0, l0);
        split1(t[2 * kp + 1][nl], h1, l1);
        int o = (n0 + nl) * (D / 2) + (k0 >> 1) + kp;
        dh[o] = pack2(h0, h1);
        dl[o] = pack2(l0, l1);
    }
}

// ================ bf16 3-term GEMM ==========================================
#define GBM 128
#define GBN 128
#define GBK 32            // bf16 elems per k-iter (2 k16 mma steps)
#define KP  (GBK / 2)     // 16 uint32 pairs per row per iter
#define NKB (D / GBK)     // 32
#define TST 20            // smem row stride in uint32 (bank-conflict-free)

#define GEMM_BODY(gAh, gAl, gBh, gBl, AROW_EXPR)                                   \
    __shared__ uint32_t Ash[GBM][TST], Asl[GBM][TST];                              \
    __shared__ uint32_t Bsh[GBN][TST], Bsl[GBN][TST];                              \
    const int tid  = threadIdx.x;                                                  \
    const int lane = tid & 31;                                                     \
    const int wid  = tid >> 5;                                                     \
    const int warp_m = (wid >> 2) * 64;                                            \
    const int warp_n = (wid & 3) * 32;                                             \
    const int m0 = blockIdx.y * GBM;                                               \
    const int n0 = blockIdx.x * GBN;                                               \
    float c[4][4][4] = {};                                                         \
    uint32_t pah[8], pal[8], pbh[8], pbl[8];                                       \
    {                                                                              \
        const int kcol = 0;                                                        \
        _Pragma("unroll")                                                          \
        for (int i = 0; i < 8; i++) {                                              \
            int idx = tid + i * 256;                                               \
            int r = idx >> 4, kp = idx & 15;                                       \
            int arow = AROW_EXPR;                                                  \
            pah[i] = gAh[arow * (D / 2) + kcol + kp];                              \
            pal[i] = gAl[arow * (D / 2) + kcol + kp];                              \
            pbh[i] = gBh[(n0 + r) * (D / 2) + kcol + kp];                          \
            pbl[i] = gBl[(n0 + r) * (D / 2) + kcol + kp];                          \
        }                                                                          \
    }                                                                              \
    for (int kb = 0; kb < NKB; kb++) {                                             \
        _Pragma("unroll")                                                          \
        for (int i = 0; i < 8; i++) {                                              \
            int idx = tid + i * 256;                                               \
            int r = idx >> 4, kp = idx & 15;                                       \
            Ash[r][kp] = pah[i]; Asl[r][kp] = pal[i];                              \
            Bsh[r][kp] = pbh[i]; Bsl[r][kp] = pbl[i];                              \
        }                                                                          \
        __syncthreads();                                                           \
        if (kb + 1 < NKB) {                                                        \
            const int kcol = (kb + 1) * KP;                                        \
            _Pragma("unroll")                                                      \
            for (int i = 0; i < 8; i++) {                                          \
                int idx = tid + i * 256;                                           \
                int r = idx >> 4, kp = idx & 15;                                   \
                int arow = AROW_EXPR;                                              \
                pah[i] = gAh[arow * (D / 2) + kcol + kp];                          \
                pal[i] = gAl[arow * (D / 2) + kcol + kp];                          \
                pbh[i] = gBh[(n0 + r) * (D / 2) + kcol + kp];                      \
                pbl[i] = gBl[(n0 + r) * (D / 2) + kcol + kp];                      \
            }                                                                      \
        }                                                                          \
        _Pragma("unroll")                                                          \
        for (int ks = 0; ks < 2; ks++) {                                           \
            const int kp0 = ks * 8;                                                \
            uint32_t ah[4][4], al[4][4], bh[4][2], bl[4][2];                       \
            _Pragma("unroll")                                                      \
            for (int t = 0; t < 4; t++) {                                          \
                int r = warp_m + t * 16 + (lane >> 2);                             \
                int q = kp0 + (lane & 3);                                          \
                ah[t][0] = Ash[r][q];     al[t][0] = Asl[r][q];                    \
                ah[t][1] = Ash[r + 8][q]; al[t][1] = Asl[r + 8][q];                \
                ah[t][2] = Ash[r][q + 4]; al[t][2] = Asl[r][q + 4];                \
                ah[t][3] = Ash[r + 8][q + 4]; al[t][3] = Asl[r + 8][q + 4];        \
            }                                                                      \
            _Pragma("unroll")                                                      \
            for (int u = 0; u < 4; u++) {                                          \
                int n = warp_n + u * 8 + (lane >> 2);                              \
                int q = kp0 + (lane & 3);                                          \
                bh[u][0] = Bsh[n][q];     bh[u][1] = Bsh[n][q + 4];                \
                bl[u][0] = Bsl[n][q];     bl[u][1] = Bsl[n][q + 4];                \
            }                                                                      \
            _Pragma("unroll")                                                      \
            for (int t = 0; t < 4; t++)                                            \
                _Pragma("unroll")                                                  \
                for (int u = 0; u < 4; u++) {                                      \
                    mma_bf16(c[t][u], ah[t], bh[u]);                               \
                    mma_bf16(c[t][u], ah[t], bl[u]);                               \
                    mma_bf16(c[t][u], al[t], bh[u]);                               \
                }                                                                  \
        }                                                                          \
        __syncthreads();                                                           \
    }

// ---- Kernel 1: fused QKV projection, epilogue -> packed bf16 hi/lo ---------
__global__ __launch_bounds__(256, 1)
void qkv_mma_kernel(const float* __restrict__ bq, const float* __restrict__ bk,
                    const float* __restrict__ bv)
{
    const float* bias; uint32_t* outH; uint32_t* outL; float scale;
    const uint32_t* wh = g_Wth + blockIdx.z * (D * D / 2);
    const uint32_t* wl = g_Wtl + blockIdx.z * (D * D / 2);
    if (blockIdx.z == 0)      { bias = bq; outH = g_Qh; outL = g_Ql; scale = 0.125f; }
    else if (blockIdx.z == 1) { bias = bk; outH = g_Kh; outL = g_Kl; scale = 1.0f; }
    else                      { bias = bv; outH = g_Vh; outL = g_Vl; scale = 1.0f; }

    GEMM_BODY(g_Xh, g_Xl, wh, wl, (m0 + r))

    #pragma unroll
    for (int t = 0; t < 4; t++) {
        int r = warp_m + t * 16 + (lane >> 2);
        #pragma unroll
        for (int half = 0; half < 2; half++) {
            int m = m0 + r + half * 8;
            int bb = m >> 11, s = m & (SQ - 1);
            #pragma unroll
            for (int u = 0; u < 4; u++) {
                int n = n0 + warp_n + u * 8 + 2 * (lane & 3);
                int h = n >> 6, dd = n & (HD - 1);
                float v0 = (c[t][u][half * 2 + 0] + bias[n])     * scale;
                float v1 = (c[t][u][half * 2 + 1] + bias[n + 1]) * scale;
                __nv_bfloat16 h0, l0, h1, l1;
                split1(v0, h0, l0); split1(v1, h1, l1);
                int idx = ((bb * H + h) * SQ + s) * 32 + (dd >> 1);
                outH[idx] = pack2(h0, h1);
                outL[idx] = pack2(l0, l1);
            }
        }
    }
}

// ---- Kernel 3: output projection ------------------------------------------
__global__ __launch_bounds__(256, 1)
void out_mma_kernel(const float* __restrict__ bo, float* __restrict__ Y)
{
    const uint32_t* wh = g_Wth + 3 * (D * D / 2);
    const uint32_t* wl = g_Wtl + 3 * (D * D / 2);

    GEMM_BODY(g_Oh, g_Ol, wh, wl, (m0 + r))

    #pragma unroll
    for (int t = 0; t < 4; t++) {
        int r = warp_m + t * 16 + (lane >> 2);
        #pragma unroll
        for (int half = 0; half < 2; half++) {
            int m = m0 + r + half * 8;
            #pragma unroll
            for (int u = 0; u < 4; u++) {
                int n = n0 + warp_n + u * 8 + 2 * (lane & 3);
                Y[m * D + n]     = c[t][u][half * 2 + 0] + bo[n];
                Y[m * D + n + 1] = c[t][u][half * 2 + 1] + bo[n + 1];
            }
        }
    }
}

// ========== Kernel 2: flash attention, split-bf16 mma =======================
// 128 threads = 4 warps; each warp owns 16 query rows; CTA tile = 64 q rows.
// KV streamed in 64-row tiles. K/V smem rows stride 36 words (conflict-free).
__global__ __launch_bounds__(128)
void attn_mma_kernel()
{
    __shared__ uint32_t Ksh[64][36], Ksl[64][36];
    __shared__ uint32_t Vsh[64][36], Vsl[64][36];

    const int bh = blockIdx.y;
    const int q0 = blockIdx.x * 64;
    const int tid = threadIdx.x, lane = tid & 31, wid = tid >> 5;
    const int qr = lane >> 2, qc = lane & 3;
    const int row0 = q0 + wid * 16 + qr;        // low fragment row (global s)

    // Q fragments (hi/lo), 4 k16 steps over HD=64
    uint32_t qfh[4][4], qfl[4][4];
    {
        const uint32_t* ph = g_Qh + (bh * SQ + row0) * 32 + qc;
        const uint32_t* pl = g_Ql + (bh * SQ + row0) * 32 + qc;
        #pragma unroll
        for (int k = 0; k < 4; k++) {
            qfh[k][0] = ph[k * 8];     qfh[k][1] = ph[k * 8 + 256];
            qfh[k][2] = ph[k * 8 + 4]; qfh[k][3] = ph[k * 8 + 260];
            qfl[k][0] = pl[k * 8];     qfl[k][1] = pl[k * 8 + 256];
            qfl[k][2] = pl[k * 8 + 4]; qfl[k][3] = pl[k * 8 + 260];
        }
    }

    float o[8][4] = {};
    float m0r = -1e30f, m1r = -1e30f, l0r = 0.f, l1r = 0.f;

    const uint32_t* KhG = g_Kh + bh * SQ * 32;
    const uint32_t* KlG = g_Kl + bh * SQ * 32;
    const uint32_t* VhG = g_Vh + bh * SQ * 32;
    const uint32_t* VlG = g_Vl + bh * SQ * 32;

    const uint32_t vbh = smem_u32(Vsh) + (lane & 15) * 144;
    const uint32_t vbl = smem_u32(Vsl) + (lane & 15) * 144;

    for (int kv0 = 0; kv0 < SQ; kv0 += 64) {
        #pragma unroll
        for (int i = 0; i < 16; i++) {
            int idx = tid + i * 128;
            int kv = idx >> 5, p = idx & 31;
            int g = (kv0 + kv) * 32 + p;
            Ksh[kv][p] = KhG[g]; Ksl[kv][p] = KlG[g];
            Vsh[kv][p] = VhG[g]; Vsl[kv][p] = VlG[g];
        }
        __syncthreads();

        // S = Q K^T (3-term), 8 n-tiles of 8 kv cols
        float sc[8][4];
        #pragma unroll
        for (int j = 0; j < 8; j++)
            sc[j][0] = sc[j][1] = sc[j][2] = sc[j][3] = 0.f;
        #pragma unroll
        for (int k = 0; k < 4; k++) {
            #pragma unroll
            for (int j = 0; j < 8; j++) {
                int kvrow = j * 8 + qr;
                uint32_t bh2[2], bl2[2];
                bh2[0] = Ksh[kvrow][k * 8 + qc]; bh2[1] = Ksh[kvrow][k * 8 + qc + 4];
                bl2[0] = Ksl[kvrow][k * 8 + qc]; bl2[1] = Ksl[kvrow][k * 8 + qc + 4];
                mma_bf16(sc[j], qfh[k], bh2);
                mma_bf16(sc[j], qfl[k], bh2);
                mma_bf16(sc[j], qfh[k], bl2);
            }
        }

        // online softmax (rows row0, row0+8); quad reduction via shfl
        float t0 = -1e30f, t1 = -1e30f;
        #pragma unroll
        for (int j = 0; j < 8; j++) {
            t0 = fmaxf(t0, fmaxf(sc[j][0], sc[j][1]));
            t1 = fmaxf(t1, fmaxf(sc[j][2], sc[j][3]));
        }
        t0 = fmaxf(t0, __shfl_xor_sync(0xffffffffu, t0, 1));
        t0 = fmaxf(t0, __shfl_xor_sync(0xffffffffu, t0, 2));
        t1 = fmaxf(t1, __shfl_xor_sync(0xffffffffu, t1, 1));
        t1 = fmaxf(t1, __shfl_xor_sync(0xffffffffu, t1, 2));
        float mn0 = fmaxf(m0r, t0), mn1 = fmaxf(m1r, t1);
        float cr0 = __expf(m0r - mn0), cr1 = __expf(m1r - mn1);
        m0r = mn0; m1r = mn1;

        float rs0 = 0.f, rs1 = 0.f;
        #pragma unroll
        for (int j = 0; j < 8; j++) {
            sc[j][0] = __expf(sc[j][0] - mn0);
            sc[j][1] = __expf(sc[j][1] - mn0);
            sc[j][2] = __expf(sc[j][2] - mn1);
            sc[j][3] = __expf(sc[j][3] - mn1);
            rs0 += sc[j][0] + sc[j][1];
            rs1 += sc[j][2] + sc[j][3];
        }
        rs0 += __shfl_xor_sync(0xffffffffu, rs0, 1);
        rs0 += __shfl_xor_sync(0xffffffffu, rs0, 2);
        rs1 += __shfl_xor_sync(0xffffffffu, rs1, 1);
        rs1 += __shfl_xor_sync(0xffffffffu, rs1, 2);
        l0r = l0r * cr0 + rs0;
        l1r = l1r * cr1 + rs1;

        #pragma unroll
        for (int u = 0; u < 8; u++) {
            o[u][0] *= cr0; o[u][1] *= cr0; o[u][2] *= cr1; o[u][3] *= cr1;
        }

        // O += P V  (P split hi/lo, V hi/lo via ldmatrix.trans; 3-term)
        #pragma unroll
        for (int k = 0; k < 4; k++) {
            uint32_t pfh[4], pfl[4];
            #pragma unroll
            for (int half = 0; half < 2; half++) {
                int j = 2 * k + half;
                __nv_bfloat16 h0, l0, h1, l1, h2, l2, h3, l3;
                split1(sc[j][0], h0, l0); split1(sc[j][1], h1, l1);
                split1(sc[j][2], h2, l2); split1(sc[j][3], h3, l3);
                pfh[half * 2 + 0] = pack2(h0, h1); pfh[half * 2 + 1] = pack2(h2, h3);
                pfl[half * 2 + 0] = pack2(l0, l1); pfl[half * 2 + 1] = pack2(l2, l3);
            }
            #pragma unroll
            for (int u = 0; u < 8; u++) {
                uint32_t vh2[2], vl2[2];
                ldmx2t(vh2[0], vh2[1], vbh + k * 2304 + u * 16);
                ldmx2t(vl2[0], vl2[1], vbl + k * 2304 + u * 16);
                mma_bf16(o[u], pfh, vh2);
                mma_bf16(o[u], pfl, vh2);
                mma_bf16(o[u], pfh, vl2);
            }
        }
        __syncthreads();
    }

    // epilogue: normalize, split hi/lo, write [m][k/2] for out projection
    float il0 = 1.f / l0r, il1 = 1.f / l1r;
    int bb = bh >> 4, hh = bh & 15;
    uint32_t* OH = g_Oh + (bb * SQ + row0) * 512 + hh * 32;
    uint32_t* OL = g_Ol + (bb * SQ + row0) * 512 + hh * 32;
    #pragma unroll
    for (int u = 0; u < 8; u++) {
        int col = u * 4 + qc;
        __nv_bfloat16 h0, l0, h1, l1;
        split1(o[u][0] * il0, h0, l0); split1(o[u][1] * il0, h1, l1);
        OH[col] = pack2(h0, h1); OL[col] = pack2(l0, l1);
        split1(o[u][2] * il1, h0, l0); split1(o[u][3] * il1, h1, l1);
        OH[512 * 8 + col] = pack2(h0, h1); OL[512 * 8 + col] = pack2(l0, l1);
    }
}

// ---------------------------------------------------------------------------
extern "C" void kernel_launch(void* const* d_in, const int* in_sizes, int n_in,
                              void* d_out, int out_size)
{
    const float* X  = (const float*)d_in[0];
    const float* Wq = (const float*)d_in[1];
    const float* bq = (const float*)d_in[2];
    const float* Wk = (const float*)d_in[3];
    const float* bk = (const float*)d_in[4];
    const float* Wv = (const float*)d_in[5];
    const float* bv = (const float*)d_in[6];
    const float* Wo = (const float*)d_in[7];
    const float* bo = (const float*)d_in[8];
    float* Y = (float*)d_out;

    split_x_kernel<<<M * D / 2 / 256, 256>>>(X);
    dim3 gW(D / 32, D / 32, 4);
    split_w_kernel<<<gW, 256>>>(Wq, Wk, Wv, Wo);

    dim3 gQKV(D / GBN, M / GBM, 3);                // 8 x 32 x 3
    qkv_mma_kernel<<<gQKV, 256>>>(bq, bk, bv);

    dim3 gAttn(SQ / 64, B * H);                    // 32 x 32
    attn_mma_kernel<<<gAttn, 128>>>();

    dim3 gOut(D / GBN, M / GBM);                   // 8 x 32
    out_mma_kernel<<<gOut, 256>>>(bo, Y);
}